// round 5
// baseline (speedup 1.0000x reference)
#include <cuda_runtime.h>
#include <math.h>
#include <stdint.h>

#define B_  4
#define S_  2048
#define D_  768
#define H_  12
#define HD_ 64
#define N3_ (3*D_)
#define M_  (B_*S_)

// Scratch (allocation-free rule: __device__ globals)
__device__ float g_q[B_*H_*S_*HD_];     // [b,h,s,d]  tf32-rounded
__device__ float g_k[B_*H_*S_*HD_];
__device__ float g_v[B_*H_*S_*HD_];
__device__ float g_attn[M_*D_];         // [b,s, h*64+d]  tf32-rounded
__device__ float g_x[M_*D_];            // tf32-rounded x
__device__ float g_wq[D_*N3_];          // tf32-rounded w_qkv
__device__ float g_wp[D_*D_];           // tf32-rounded w_proj

// ---------------------------------------------------------------------------
// helpers
// ---------------------------------------------------------------------------
__device__ __forceinline__ float tf32r(float x) {
    uint32_t u;
    asm("cvt.rna.tf32.f32 %0, %1;" : "=r"(u) : "f"(x));
    return __uint_as_float(u);
}
// NOTE: non-volatile — pure function of inputs, lets ptxas interleave HMMA chains
__device__ __forceinline__ void mma8(float c[4], const uint32_t a[4], const uint32_t b[2]) {
    asm("mma.sync.aligned.m16n8k8.row.col.f32.tf32.tf32.f32 "
        "{%0,%1,%2,%3},{%4,%5,%6,%7},{%8,%9},{%0,%1,%2,%3};"
        : "+f"(c[0]), "+f"(c[1]), "+f"(c[2]), "+f"(c[3])
        : "r"(a[0]), "r"(a[1]), "r"(a[2]), "r"(a[3]), "r"(b[0]), "r"(b[1]));
}
__device__ __forceinline__ uint32_t fbits(float x) { return __float_as_uint(x); }
__device__ __forceinline__ void cp16(uint32_t sdst, const void* gsrc) {
    asm volatile("cp.async.cg.shared.global [%0], [%1], 16;" :: "r"(sdst), "l"(gsrc));
}
__device__ __forceinline__ void cp_commit() {
    asm volatile("cp.async.commit_group;" ::: "memory");
}
__device__ __forceinline__ uint32_t s2u(const void* p) {
    return (uint32_t)__cvta_generic_to_shared(p);
}

// ---------------------------------------------------------------------------
// Pre-round inputs to tf32 bit patterns (enables cvt-free cp.async GEMMs)
// ---------------------------------------------------------------------------
__global__ void pre_round(const float* __restrict__ x,
                          const float* __restrict__ wq,
                          const float* __restrict__ wp)
{
    int y = blockIdx.y;
    const float4* src; float4* dst; int n4;
    if (y == 0)      { src = (const float4*)x;  dst = (float4*)g_x;  n4 = (M_*D_)/4;   }
    else if (y == 1) { src = (const float4*)wq; dst = (float4*)g_wq; n4 = (D_*N3_)/4;  }
    else             { src = (const float4*)wp; dst = (float4*)g_wp; n4 = (D_*D_)/4;   }
    for (int i = blockIdx.x * blockDim.x + threadIdx.x; i < n4;
         i += gridDim.x * blockDim.x) {
        float4 v = src[i];
        v.x = tf32r(v.x); v.y = tf32r(v.y); v.z = tf32r(v.z); v.w = tf32r(v.w);
        dst[i] = v;
    }
}

// ---------------------------------------------------------------------------
// tf32 GEMM, cp.async 2-stage: C[M x N] = A[M x 768] @ W[768 x N] + bias
// CTA 128x128x32, 256 threads, 8 warps (4x2), warp tile 32x64, 2 CTAs/SM.
// ---------------------------------------------------------------------------
#define AP 36
#define BP 136
#define ASTF (128*AP)
#define BSTF (32*BP)
#define STG  (ASTF + BSTF)

template<bool QKV>
__global__ __launch_bounds__(256, 2) void gemm_tf32(
    const float* __restrict__ bias, float* __restrict__ C, int N)
{
    extern __shared__ float sm[];
    const int K = D_;
    int tid = threadIdx.x, bx = blockIdx.x, by = blockIdx.y;
    int lane = tid & 31, wid = tid >> 5, lg = lane >> 2, lq = lane & 3;
    int wm = (wid >> 1) * 32, wn = (wid & 1) * 64;

    const float* Abase = QKV ? (const float*)g_x  : (const float*)g_attn;
    const float* Bbase = QKV ? (const float*)g_wq : (const float*)g_wp;

    int ar = tid >> 1, ac = (tid & 1) * 16;
    int br = tid >> 3, bc4 = (tid & 7) * 4;
    const float* asrc = Abase + (size_t)(by * 128 + ar) * K + ac;
    const float* bsrc = Bbase + (size_t)br * N + bx * 128 + bc4;
    uint32_t abase = s2u(sm) + (ar * AP + ac) * 4;
    uint32_t bbase = s2u(sm) + (ASTF + br * BP + bc4) * 4;

    float acc[2][8][4];
    #pragma unroll
    for (int mt = 0; mt < 2; mt++)
        #pragma unroll
        for (int nt = 0; nt < 8; nt++)
            #pragma unroll
            for (int i = 0; i < 4; i++) acc[mt][nt][i] = 0.f;

    {
        #pragma unroll
        for (int j = 0; j < 4; j++) cp16(abase + j * 16, asrc + j * 4);
        #pragma unroll
        for (int j = 0; j < 4; j++) cp16(bbase + j * 128, bsrc + j * 32);
        cp_commit();
    }

    for (int it = 0; it < 24; it++) {
        if (it < 23) {
            int st = (it + 1) & 1;
            const float* as2 = asrc + (it + 1) * 32;
            const float* bs2 = bsrc + (size_t)(it + 1) * 32 * N;
            uint32_t ad = abase + st * (STG * 4);
            uint32_t bd = bbase + st * (STG * 4);
            #pragma unroll
            for (int j = 0; j < 4; j++) cp16(ad + j * 16, as2 + j * 4);
            #pragma unroll
            for (int j = 0; j < 4; j++) cp16(bd + j * 128, bs2 + j * 32);
            cp_commit();
            asm volatile("cp.async.wait_group 1;" ::: "memory");
        } else {
            asm volatile("cp.async.wait_group 0;" ::: "memory");
        }
        __syncthreads();

        const float* As = sm + (it & 1) * STG;
        const float* Bs = As + ASTF;

        #pragma unroll
        for (int kk = 0; kk < 4; kk++) {
            int kr = kk * 8;
            uint32_t af[2][4], bf[8][2];
            #pragma unroll
            for (int mt = 0; mt < 2; mt++) {
                int r0 = (wm + mt * 16 + lg) * AP;
                af[mt][0] = fbits(As[r0          + kr + lq    ]);
                af[mt][1] = fbits(As[r0 + 8 * AP + kr + lq    ]);
                af[mt][2] = fbits(As[r0          + kr + lq + 4]);
                af[mt][3] = fbits(As[r0 + 8 * AP + kr + lq + 4]);
            }
            #pragma unroll
            for (int nt = 0; nt < 8; nt++) {
                bf[nt][0] = fbits(Bs[(kr + lq    ) * BP + wn + nt * 8 + lg]);
                bf[nt][1] = fbits(Bs[(kr + lq + 4) * BP + wn + nt * 8 + lg]);
            }
            #pragma unroll
            for (int mt = 0; mt < 2; mt++)
                #pragma unroll
                for (int nt = 0; nt < 8; nt++)
                    mma8(acc[mt][nt], af[mt], bf[nt]);
        }
        __syncthreads();
    }

    #pragma unroll
    for (int mt = 0; mt < 2; mt++) {
        #pragma unroll
        for (int rp = 0; rp < 2; rp++) {
            int m = by * 128 + wm + mt * 16 + lg + rp * 8;
            if (QKV) {
                int bb = m >> 11;
                int ss = m & (S_ - 1);
                #pragma unroll
                for (int nt = 0; nt < 8; nt++) {
                    int n = bx * 128 + wn + nt * 8 + 2 * lq;
                    int which = n / D_;
                    int rem = n - which * D_;
                    int hh = rem >> 6, dd = rem & 63;
                    float2 v;
                    v.x = tf32r(acc[mt][nt][rp*2 + 0] + bias[n]);
                    v.y = tf32r(acc[mt][nt][rp*2 + 1] + bias[n + 1]);
                    float* dst = (which == 0) ? g_q : ((which == 1) ? g_k : g_v);
                    *(float2*)&dst[(((size_t)(bb * H_ + hh) * S_ + ss) << 6) + dd] = v;
                }
            } else {
                #pragma unroll
                for (int nt = 0; nt < 8; nt++) {
                    int n = bx * 128 + wn + nt * 8 + 2 * lq;
                    float2 v;
                    v.x = acc[mt][nt][rp*2 + 0] + bias[n];
                    v.y = acc[mt][nt][rp*2 + 1] + bias[n + 1];
                    *(float2*)&C[(size_t)m * D_ + n] = v;
                }
            }
        }
    }
}

// ---------------------------------------------------------------------------
// Flash attention, causal, tf32 mma, double-buffered K/V (cp.async 2-stage).
// One block = (b, h, 64-row q tile); 128 threads; warp w owns rows [w*16,+16).
// SMEM: K[2][64][68], V[2][64][68], Ps[64][68]  (87040 B, 2 CTAs/SM)
// ---------------------------------------------------------------------------
#define TSZ (64*68)

__global__ __launch_bounds__(128) void flash_attn_tf32()
{
    extern __shared__ float sm[];
    float* Kst[2] = { sm,            sm + TSZ     };
    float* Vst[2] = { sm + 2*TSZ,    sm + 3*TSZ   };
    float* Ps = sm + 4*TSZ;

    int bid = blockIdx.x;
    int qt = 31 - (bid & 31);          // heavy blocks first
    int h  = (bid >> 5) % H_;
    int b  = bid / (32 * H_);
    int tid = threadIdx.x;
    int lane = tid & 31, w = tid >> 5, lg = lane >> 2, lq = lane & 3;
    int q0 = qt * 64;
    const float scale = 0.125f;

    const float* Qg = g_q + (size_t)(b * H_ + h) * S_ * HD_;
    const float* Kg = g_k + (size_t)(b * H_ + h) * S_ * HD_;
    const float* Vg = g_v + (size_t)(b * H_ + h) * S_ * HD_;

    int r = tid >> 1, c0 = (tid & 1) * 32;
    uint32_t ks_u[2] = { s2u(Kst[0]) + (r*68 + c0)*4, s2u(Kst[1]) + (r*68 + c0)*4 };
    uint32_t vs_u[2] = { s2u(Vst[0]) + (r*68 + c0)*4, s2u(Vst[1]) + (r*68 + c0)*4 };
    const float* kg_row = Kg + (size_t)r * 64 + c0;
    const float* vg_row = Vg + (size_t)r * 64 + c0;

    // Prefetch k-tile 0 into stage 0
    #pragma unroll
    for (int j = 0; j < 8; j++) cp16(ks_u[0] + j*16, kg_row + j*4);
    #pragma unroll
    for (int j = 0; j < 8; j++) cp16(vs_u[0] + j*16, vg_row + j*4);
    cp_commit();

    // Stage Q tile (pre-rounded; *0.125 exact) into Ps, pull fragments
    #pragma unroll
    for (int j = 0; j < 8; j++) {
        float4 q4 = *(const float4*)(Qg + (size_t)(q0 + r) * 64 + c0 + j * 4);
        q4.x *= scale; q4.y *= scale; q4.z *= scale; q4.w *= scale;
        *(float4*)&Ps[r * 68 + c0 + j * 4] = q4;
    }
    __syncthreads();

    uint32_t qf[8][4];
    #pragma unroll
    for (int kk = 0; kk < 8; kk++) {
        qf[kk][0] = fbits(Ps[(w*16 + lg    ) * 68 + kk*8 + lq    ]);
        qf[kk][1] = fbits(Ps[(w*16 + lg + 8) * 68 + kk*8 + lq    ]);
        qf[kk][2] = fbits(Ps[(w*16 + lg    ) * 68 + kk*8 + lq + 4]);
        qf[kk][3] = fbits(Ps[(w*16 + lg + 8) * 68 + kk*8 + lq + 4]);
    }
    __syncthreads();

    float mrow[2] = {-INFINITY, -INFINITY};
    float lrow[2] = {0.f, 0.f};
    float o[8][4];
    #pragma unroll
    for (int nt = 0; nt < 8; nt++)
        #pragma unroll
        for (int i = 0; i < 4; i++) o[nt][i] = 0.f;

    for (int kt = 0; kt <= qt; kt++) {
        int st = kt & 1;
        // Prefetch next tile into the buffer freed by iteration kt-1
        if (kt < qt) {
            size_t koff = (size_t)(kt + 1) * 64 * 64;
            #pragma unroll
            for (int j = 0; j < 8; j++) cp16(ks_u[st^1] + j*16, kg_row + koff + j*4);
            #pragma unroll
            for (int j = 0; j < 8; j++) cp16(vs_u[st^1] + j*16, vg_row + koff + j*4);
            cp_commit();
            asm volatile("cp.async.wait_group 1;" ::: "memory");
        } else {
            asm volatile("cp.async.wait_group 0;" ::: "memory");
        }
        __syncthreads();

        const float* Ks = Kst[st];
        const float* Vs = Vst[st];

        // S = (Q*scale) @ K^T
        float s[8][4];
        #pragma unroll
        for (int nt = 0; nt < 8; nt++)
            #pragma unroll
            for (int i = 0; i < 4; i++) s[nt][i] = 0.f;

        #pragma unroll
        for (int kk = 0; kk < 8; kk++) {
            uint32_t bv[8][2];
            #pragma unroll
            for (int nt = 0; nt < 8; nt++) {
                bv[nt][0] = fbits(Ks[(nt*8 + lg) * 68 + kk*8 + lq    ]);
                bv[nt][1] = fbits(Ks[(nt*8 + lg) * 68 + kk*8 + lq + 4]);
            }
            #pragma unroll
            for (int nt = 0; nt < 8; nt++)
                mma8(s[nt], qf[kk], bv[nt]);
        }

        if (kt == qt) {   // diagonal tile: causal mask
            #pragma unroll
            for (int nt = 0; nt < 8; nt++)
                #pragma unroll
                for (int rp = 0; rp < 2; rp++)
                    #pragma unroll
                    for (int j = 0; j < 2; j++) {
                        int col = nt*8 + 2*lq + j;
                        int row = w*16 + lg + rp*8;
                        if (col > row) s[nt][rp*2 + j] = -INFINITY;
                    }
        }

        // Online softmax
        #pragma unroll
        for (int rp = 0; rp < 2; rp++) {
            float mt = -INFINITY;
            #pragma unroll
            for (int nt = 0; nt < 8; nt++)
                mt = fmaxf(mt, fmaxf(s[nt][rp*2], s[nt][rp*2 + 1]));
            mt = fmaxf(mt, __shfl_xor_sync(0xffffffffu, mt, 1));
            mt = fmaxf(mt, __shfl_xor_sync(0xffffffffu, mt, 2));
            float mnew = fmaxf(mrow[rp], mt);
            float alpha = __expf(mrow[rp] - mnew);
            float rs = 0.f;
            #pragma unroll
            for (int nt = 0; nt < 8; nt++) {
                float e0 = __expf(s[nt][rp*2]     - mnew);
                float e1 = __expf(s[nt][rp*2 + 1] - mnew);
                s[nt][rp*2] = e0; s[nt][rp*2 + 1] = e1;
                rs += e0 + e1;
            }
            rs += __shfl_xor_sync(0xffffffffu, rs, 1);
            rs += __shfl_xor_sync(0xffffffffu, rs, 2);
            lrow[rp] = lrow[rp] * alpha + rs;
            mrow[rp] = mnew;
            #pragma unroll
            for (int nt = 0; nt < 8; nt++) {
                o[nt][rp*2]     *= alpha;
                o[nt][rp*2 + 1] *= alpha;
            }
            #pragma unroll
            for (int nt = 0; nt < 8; nt++) {
                float2 pv;
                pv.x = tf32r(s[nt][rp*2]);
                pv.y = tf32r(s[nt][rp*2 + 1]);
                *(float2*)&Ps[(w*16 + lg + rp*8) * 68 + nt*8 + 2*lq] = pv;
            }
        }
        __syncwarp();

        // O += P @ V
        #pragma unroll
        for (int kk = 0; kk < 8; kk++) {
            uint32_t pa[4];
            pa[0] = fbits(Ps[(w*16 + lg    ) * 68 + kk*8 + lq    ]);
            pa[1] = fbits(Ps[(w*16 + lg + 8) * 68 + kk*8 + lq    ]);
            pa[2] = fbits(Ps[(w*16 + lg    ) * 68 + kk*8 + lq + 4]);
            pa[3] = fbits(Ps[(w*16 + lg + 8) * 68 + kk*8 + lq + 4]);
            uint32_t bv[8][2];
            #pragma unroll
            for (int nt = 0; nt < 8; nt++) {
                bv[nt][0] = fbits(Vs[(kk*8 + lq    ) * 68 + nt*8 + lg]);
                bv[nt][1] = fbits(Vs[(kk*8 + lq + 4) * 68 + nt*8 + lg]);
            }
            #pragma unroll
            for (int nt = 0; nt < 8; nt++)
                mma8(o[nt], pa, bv[nt]);
        }
        __syncthreads();   // all reads of stage st done -> free for kt+1 prefetch
    }

    // Normalize, tf32-round (proj A operand), write [b, s, h*64+d]
    #pragma unroll
    for (int rp = 0; rp < 2; rp++) {
        float inv = 1.f / lrow[rp];
        int row = q0 + w*16 + lg + rp*8;
        #pragma unroll
        for (int nt = 0; nt < 8; nt++) {
            int d = nt*8 + 2*lq;
            float2 v;
            v.x = tf32r(o[nt][rp*2]     * inv);
            v.y = tf32r(o[nt][rp*2 + 1] * inv);
            *(float2*)&g_attn[((size_t)(b * S_ + row)) * D_ + h * 64 + d] = v;
        }
    }
}

// ---------------------------------------------------------------------------
extern "C" void kernel_launch(void* const* d_in, const int* in_sizes, int n_in,
                              void* d_out, int out_size)
{
    const float* x      = (const float*)d_in[0];
    const float* b_qkv  = (const float*)d_in[2];
    const float* b_proj = (const float*)d_in[4];
    float* out = (float*)d_out;

    pre_round<<<dim3(256, 3), 256>>>(x, (const float*)d_in[1], (const float*)d_in[3]);

    int gsmem = 2 * STG * (int)sizeof(float);   // 71680 B
    cudaFuncSetAttribute(gemm_tf32<true>,
                         cudaFuncAttributeMaxDynamicSharedMemorySize, gsmem);
    cudaFuncSetAttribute(gemm_tf32<false>,
                         cudaFuncAttributeMaxDynamicSharedMemorySize, gsmem);

    dim3 g1(N3_ / 128, M_ / 128);
    gemm_tf32<true><<<g1, 256, gsmem>>>(b_qkv, nullptr, N3_);

    int asmem = 5 * TSZ * (int)sizeof(float);   // 87040 B
    cudaFuncSetAttribute(flash_attn_tf32,
                         cudaFuncAttributeMaxDynamicSharedMemorySize, asmem);
    flash_attn_tf32<<<B_ * H_ * (S_ / 64), 128, asmem>>>();

    dim3 g2(D_ / 128, M_ / 128);
    gemm_tf32<false><<<g2, 256, gsmem>>>(b_proj, out, D_);
}

// round 7
// speedup vs baseline: 1.4384x; 1.4384x over previous
#include <cuda_runtime.h>
#include <cuda_fp16.h>
#include <math.h>
#include <stdint.h>

#define B_  4
#define S_  2048
#define D_  768
#define H_  12
#define HD_ 64
#define N3_ (3*D_)
#define M_  (B_*S_)

// Scratch (allocation-free rule: __device__ globals)
__device__ __half g_q[B_*H_*S_*HD_];    // [b,h,s,d] fp16
__device__ __half g_k[B_*H_*S_*HD_];
__device__ float  g_v[B_*H_*S_*HD_];    // fp32, tf32-rounded
__device__ __half g_attn[M_*D_];        // [b,s, h*64+d] fp16
__device__ __half g_x[M_*D_];           // fp16 x
__device__ __half g_wq[N3_*D_];         // w_qkv^T  [N3][K] fp16
__device__ __half g_wp[D_*D_];          // w_proj^T [N][K]  fp16

// ---------------------------------------------------------------------------
// helpers
// ---------------------------------------------------------------------------
__device__ __forceinline__ float tf32r(float x) {
    uint32_t u;
    asm("cvt.rna.tf32.f32 %0, %1;" : "=r"(u) : "f"(x));
    return __uint_as_float(u);
}
__device__ __forceinline__ void mma8(float c[4], const uint32_t a[4], const uint32_t b[2]) {
    asm("mma.sync.aligned.m16n8k8.row.col.f32.tf32.tf32.f32 "
        "{%0,%1,%2,%3},{%4,%5,%6,%7},{%8,%9},{%0,%1,%2,%3};"
        : "+f"(c[0]), "+f"(c[1]), "+f"(c[2]), "+f"(c[3])
        : "r"(a[0]), "r"(a[1]), "r"(a[2]), "r"(a[3]), "r"(b[0]), "r"(b[1]));
}
__device__ __forceinline__ void mma16(float c[4], const uint32_t a[4], const uint32_t b[2]) {
    asm("mma.sync.aligned.m16n8k16.row.col.f32.f16.f16.f32 "
        "{%0,%1,%2,%3},{%4,%5,%6,%7},{%8,%9},{%0,%1,%2,%3};"
        : "+f"(c[0]), "+f"(c[1]), "+f"(c[2]), "+f"(c[3])
        : "r"(a[0]), "r"(a[1]), "r"(a[2]), "r"(a[3]), "r"(b[0]), "r"(b[1]));
}
__device__ __forceinline__ uint32_t fbits(float x) { return __float_as_uint(x); }
__device__ __forceinline__ uint32_t hbits(const __half* p) {
    return *reinterpret_cast<const uint32_t*>(p);
}
__device__ __forceinline__ void cp16(uint32_t sdst, const void* gsrc) {
    asm volatile("cp.async.cg.shared.global [%0], [%1], 16;" :: "r"(sdst), "l"(gsrc));
}
__device__ __forceinline__ void cp_commit() {
    asm volatile("cp.async.commit_group;" ::: "memory");
}
__device__ __forceinline__ uint32_t s2u(const void* p) {
    return (uint32_t)__cvta_generic_to_shared(p);
}

// ---------------------------------------------------------------------------
// pre-round: x -> fp16 ; weights -> transposed [N][K] fp16
// ---------------------------------------------------------------------------
__global__ void pre_round_x(const float* __restrict__ x)
{
    const float4* src = (const float4*)x;
    __half2* dst = (__half2*)g_x;
    int n4 = (M_*D_)/4;
    for (int i = blockIdx.x * blockDim.x + threadIdx.x; i < n4;
         i += gridDim.x * blockDim.x) {
        float4 v = src[i];
        dst[i*2]   = __floats2half2_rn(v.x, v.y);
        dst[i*2+1] = __floats2half2_rn(v.z, v.w);
    }
}

__global__ void transpose_round(const float* __restrict__ src, int cols, int which)
{
    __shared__ float t[32][33];
    __half* dst = which ? g_wp : g_wq;   // [cols][768]
    int c0 = blockIdx.x * 32, r0 = blockIdx.y * 32;
    int x = threadIdx.x, y = threadIdx.y;   // 32 x 8
    #pragma unroll
    for (int i = y; i < 32; i += 8)
        t[i][x] = src[(size_t)(r0 + i) * cols + c0 + x];
    __syncthreads();
    #pragma unroll
    for (int i = y; i < 32; i += 8)
        dst[(size_t)(c0 + i) * D_ + r0 + x] = __float2half_rn(t[x][i]);
}

// ---------------------------------------------------------------------------
// fp16 GEMM, cp.async 2-stage: C[M x N] = A[M x 768] @ Wt[N x 768]^T + bias
// CTA 128x128 (k-tile 32), 256 threads, 8 warps (4x2), warp tile 32x64.
// SMEM per stage: A[128][40]h + B[128][40]h. 2 stages = 40960 B, 2 CTAs/SM.
// ---------------------------------------------------------------------------
#define GAP 40
#define GA_HALFS (128*GAP)        // one tile (A or B)
#define GSTG_HALFS (2*GA_HALFS)   // A+B per stage

template<bool QKV>
__global__ __launch_bounds__(256, 2) void gemm_h(
    const float* __restrict__ bias, float* __restrict__ C)
{
    extern __shared__ __half hsm[];
    const int K = D_;
    int tid = threadIdx.x, bx = blockIdx.x, by = blockIdx.y;
    int lane = tid & 31, wid = tid >> 5, lg = lane >> 2, lq = lane & 3;
    int wm = (wid >> 1) * 32, wn = (wid & 1) * 64;

    const __half* Ab = QKV ? (const __half*)g_x  : (const __half*)g_attn;
    const __half* Bt = QKV ? (const __half*)g_wq : (const __half*)g_wp;

    int r = tid >> 1, p = tid & 1;                  // 128 rows, 2 half-rows
    const __half* asrc = Ab + (size_t)(by * 128 + r) * K + p * 16;
    const __half* bsrc = Bt + (size_t)(bx * 128 + r) * K + p * 16;
    uint32_t a_s = s2u(hsm) + (r * GAP + p * 16) * 2;
    uint32_t b_s = s2u(hsm) + (GA_HALFS + r * GAP + p * 16) * 2;

    float acc[2][8][4];
    #pragma unroll
    for (int mt = 0; mt < 2; mt++)
        #pragma unroll
        for (int nt = 0; nt < 8; nt++)
            #pragma unroll
            for (int i = 0; i < 4; i++) acc[mt][nt][i] = 0.f;

    #define GLOAD(ch, st) do {                                  \
        uint32_t ao = a_s + (st) * (GSTG_HALFS * 2);            \
        uint32_t bo = b_s + (st) * (GSTG_HALFS * 2);            \
        const __half* ap = asrc + (ch) * 32;                    \
        const __half* bp = bsrc + (ch) * 32;                    \
        cp16(ao,      ap);     cp16(ao + 16, ap + 8);           \
        cp16(bo,      bp);     cp16(bo + 16, bp + 8);           \
        cp_commit();                                            \
    } while (0)

    GLOAD(0, 0);

    for (int it = 0; it < 24; it++) {
        if (it < 23) {
            GLOAD(it + 1, (it + 1) & 1);
            asm volatile("cp.async.wait_group 1;" ::: "memory");
        } else {
            asm volatile("cp.async.wait_group 0;" ::: "memory");
        }
        __syncthreads();

        const __half* As = hsm + (it & 1) * GSTG_HALFS;
        const __half* Bs = As + GA_HALFS;

        #pragma unroll
        for (int ks = 0; ks < 2; ks++) {
            int kr = ks * 16;
            uint32_t af[2][4], bf[8][2];
            #pragma unroll
            for (int mt = 0; mt < 2; mt++) {
                int r0 = (wm + mt * 16 + lg) * GAP;
                af[mt][0] = hbits(&As[r0           + kr + 2*lq    ]);
                af[mt][1] = hbits(&As[r0 + 8 * GAP + kr + 2*lq    ]);
                af[mt][2] = hbits(&As[r0           + kr + 2*lq + 8]);
                af[mt][3] = hbits(&As[r0 + 8 * GAP + kr + 2*lq + 8]);
            }
            #pragma unroll
            for (int nt = 0; nt < 8; nt++) {
                int nr = (wn + nt * 8 + lg) * GAP;
                bf[nt][0] = hbits(&Bs[nr + kr + 2*lq    ]);
                bf[nt][1] = hbits(&Bs[nr + kr + 2*lq + 8]);
            }
            #pragma unroll
            for (int mt = 0; mt < 2; mt++)
                #pragma unroll
                for (int nt = 0; nt < 8; nt++)
                    mma16(acc[mt][nt], af[mt], bf[nt]);
        }
        __syncthreads();
    }

    // Epilogue
    #pragma unroll
    for (int mt = 0; mt < 2; mt++) {
        #pragma unroll
        for (int rp = 0; rp < 2; rp++) {
            int m = by * 128 + wm + mt * 16 + lg + rp * 8;
            if (QKV) {
                int bb = m >> 11;
                int ss = m & (S_ - 1);
                #pragma unroll
                for (int nt = 0; nt < 8; nt++) {
                    int n = bx * 128 + wn + nt * 8 + 2 * lq;
                    int which = n / D_;
                    int rem = n - which * D_;
                    int hh = rem >> 6, dd = rem & 63;
                    float vx = acc[mt][nt][rp*2 + 0] + bias[n];
                    float vy = acc[mt][nt][rp*2 + 1] + bias[n + 1];
                    size_t idx = (((size_t)(bb * H_ + hh) * S_ + ss) << 6) + dd;
                    if (which == 2) {
                        g_v[idx]     = tf32r(vx);
                        g_v[idx + 1] = tf32r(vy);
                    } else {
                        __half* dst = (which == 0) ? g_q : g_k;
                        *(__half2*)&dst[idx] = __floats2half2_rn(vx, vy);
                    }
                }
            } else {
                #pragma unroll
                for (int nt = 0; nt < 8; nt++) {
                    int n = bx * 128 + wn + nt * 8 + 2 * lq;
                    float2 v;
                    v.x = acc[mt][nt][rp*2 + 0] + bias[n];
                    v.y = acc[mt][nt][rp*2 + 1] + bias[n + 1];
                    *(float2*)&C[(size_t)m * D_ + n] = v;
                }
            }
        }
    }
}

// ---------------------------------------------------------------------------
// Flash attention, causal. QK^T in fp16 (m16n8k16), P@V in tf32 (m16n8k8).
// One block = (b, h, 64-row q tile); 128 threads; warp w owns rows [w*16,+16).
// SMEM: Vs[64][68]f32, Ps[64][68]f32, Ks[64][72]h. qt descending.
// ---------------------------------------------------------------------------
#define TSZ (64*68)
#define KSP 72

__global__ __launch_bounds__(128) void flash_attn_h()
{
    extern __shared__ float sm[];
    float* Vs = sm;
    float* Ps = sm + TSZ;
    __half* Ks = (__half*)(sm + 2*TSZ);

    int bid = blockIdx.x;
    int qt = 31 - (bid & 31);
    int h  = (bid >> 5) % H_;
    int b  = bid / (32 * H_);
    int tid = threadIdx.x;
    int lane = tid & 31, w = tid >> 5, lg = lane >> 2, lq = lane & 3;
    int q0 = qt * 64;

    const __half* Qg = g_q + (size_t)(b * H_ + h) * S_ * HD_;
    const __half* Kg = g_k + (size_t)(b * H_ + h) * S_ * HD_;
    const float*  Vg = g_v + (size_t)(b * H_ + h) * S_ * HD_;

    // K cp.async mapping: 64 rows x 128B; thread t -> row t>>1, 4 chunks
    int kr_ = tid >> 1, kp_ = tid & 1;
    uint32_t ks_u = s2u(Ks) + (kr_ * KSP + kp_ * 32) * 2;
    const __half* kg_row = Kg + (size_t)kr_ * 64 + kp_ * 32;
    // V cp.async mapping (fp32): row t>>1, 8 chunks of 4 floats
    int vr_ = tid >> 1, vc_ = (tid & 1) * 32;
    uint32_t vs_u = s2u(Vs) + (vr_ * 68 + vc_) * 4;
    const float* vg_row = Vg + (size_t)vr_ * 64 + vc_;

    // Q fragments from global, scaled by 0.125 (exact in fp16)
    const __half2 sc2 = __floats2half2_rn(0.125f, 0.125f);
    uint32_t qf[4][4];
    {
        const __half* qr0 = Qg + (size_t)(q0 + w*16 + lg    ) * 64;
        const __half* qr1 = Qg + (size_t)(q0 + w*16 + lg + 8) * 64;
        #pragma unroll
        for (int ks = 0; ks < 4; ks++) {
            int kc = ks * 16 + 2 * lq;
            uint32_t t0 = hbits(qr0 + kc),     t1 = hbits(qr1 + kc);
            uint32_t t2 = hbits(qr0 + kc + 8), t3 = hbits(qr1 + kc + 8);
            __half2 h0 = __hmul2(*(__half2*)&t0, sc2);
            __half2 h1 = __hmul2(*(__half2*)&t1, sc2);
            __half2 h2 = __hmul2(*(__half2*)&t2, sc2);
            __half2 h3 = __hmul2(*(__half2*)&t3, sc2);
            qf[ks][0] = *(uint32_t*)&h0; qf[ks][1] = *(uint32_t*)&h1;
            qf[ks][2] = *(uint32_t*)&h2; qf[ks][3] = *(uint32_t*)&h3;
        }
    }

    float mrow[2] = {-INFINITY, -INFINITY};
    float lrow[2] = {0.f, 0.f};
    float o[8][4];
    #pragma unroll
    for (int nt = 0; nt < 8; nt++)
        #pragma unroll
        for (int i = 0; i < 4; i++) o[nt][i] = 0.f;

    for (int kt = 0; kt <= qt; kt++) {
        size_t koff = (size_t)kt * 64 * 64;
        __syncthreads();   // prior reads of Ks/Vs done
        #pragma unroll
        for (int j = 0; j < 4; j++) cp16(ks_u + j * 16, kg_row + koff + j * 8);
        #pragma unroll
        for (int j = 0; j < 8; j++) cp16(vs_u + j * 16, vg_row + koff + j * 4);
        cp_commit();
        asm volatile("cp.async.wait_group 0;" ::: "memory");
        __syncthreads();

        // S = (Q*scale) @ K^T   (fp16 mma, 4 k-steps)
        float s[8][4];
        #pragma unroll
        for (int nt = 0; nt < 8; nt++)
            #pragma unroll
            for (int i = 0; i < 4; i++) s[nt][i] = 0.f;

        #pragma unroll
        for (int ks = 0; ks < 4; ks++) {
            int kr = ks * 16 + 2 * lq;
            uint32_t bv[8][2];
            #pragma unroll
            for (int nt = 0; nt < 8; nt++) {
                int nr = (nt * 8 + lg) * KSP;
                bv[nt][0] = hbits(&Ks[nr + kr    ]);
                bv[nt][1] = hbits(&Ks[nr + kr + 8]);
            }
            #pragma unroll
            for (int nt = 0; nt < 8; nt++)
                mma16(s[nt], qf[ks], bv[nt]);
        }

        if (kt == qt) {   // diagonal tile: causal mask
            #pragma unroll
            for (int nt = 0; nt < 8; nt++)
                #pragma unroll
                for (int rp = 0; rp < 2; rp++)
                    #pragma unroll
                    for (int j = 0; j < 2; j++) {
                        int col = nt*8 + 2*lq + j;
                        int row = w*16 + lg + rp*8;
                        if (col > row) s[nt][rp*2 + j] = -INFINITY;
                    }
        }

        // Online softmax (thread owns rows lg, lg+8 of warp tile)
        #pragma unroll
        for (int rp = 0; rp < 2; rp++) {
            float mt = -INFINITY;
            #pragma unroll
            for (int nt = 0; nt < 8; nt++)
                mt = fmaxf(mt, fmaxf(s[nt][rp*2], s[nt][rp*2 + 1]));
            mt = fmaxf(mt, __shfl_xor_sync(0xffffffffu, mt, 1));
            mt = fmaxf(mt, __shfl_xor_sync(0xffffffffu, mt, 2));
            float mnew = fmaxf(mrow[rp], mt);
            float alpha = __expf(mrow[rp] - mnew);
            float rs = 0.f;
            #pragma unroll
            for (int nt = 0; nt < 8; nt++) {
                float e0 = __expf(s[nt][rp*2]     - mnew);
                float e1 = __expf(s[nt][rp*2 + 1] - mnew);
                s[nt][rp*2] = e0; s[nt][rp*2 + 1] = e1;
                rs += e0 + e1;
            }
            rs += __shfl_xor_sync(0xffffffffu, rs, 1);
            rs += __shfl_xor_sync(0xffffffffu, rs, 2);
            lrow[rp] = lrow[rp] * alpha + rs;
            mrow[rp] = mnew;
            #pragma unroll
            for (int nt = 0; nt < 8; nt++) {
                o[nt][rp*2]     *= alpha;
                o[nt][rp*2 + 1] *= alpha;
            }
            #pragma unroll
            for (int nt = 0; nt < 8; nt++) {
                float2 pv;
                pv.x = tf32r(s[nt][rp*2]);
                pv.y = tf32r(s[nt][rp*2 + 1]);
                *(float2*)&Ps[(w*16 + lg + rp*8) * 68 + nt*8 + 2*lq] = pv;
            }
        }
        __syncwarp();

        // O += P @ V   (tf32 mma, 8 k-slices)
        #pragma unroll
        for (int kk = 0; kk < 8; kk++) {
            uint32_t pa[4];
            pa[0] = fbits(Ps[(w*16 + lg    ) * 68 + kk*8 + lq    ]);
            pa[1] = fbits(Ps[(w*16 + lg + 8) * 68 + kk*8 + lq    ]);
            pa[2] = fbits(Ps[(w*16 + lg    ) * 68 + kk*8 + lq + 4]);
            pa[3] = fbits(Ps[(w*16 + lg + 8) * 68 + kk*8 + lq + 4]);
            uint32_t bv[8][2];
            #pragma unroll
            for (int nt = 0; nt < 8; nt++) {
                bv[nt][0] = fbits(Vs[(kk*8 + lq    ) * 68 + nt*8 + lg]);
                bv[nt][1] = fbits(Vs[(kk*8 + lq + 4) * 68 + nt*8 + lg]);
            }
            #pragma unroll
            for (int nt = 0; nt < 8; nt++)
                mma8(o[nt], pa, bv[nt]);
        }
        __syncwarp();
    }

    // Normalize, fp16-round (proj A operand), write [b, s, h*64+d]
    #pragma unroll
    for (int rp = 0; rp < 2; rp++) {
        float inv = 1.f / lrow[rp];
        int row = q0 + w*16 + lg + rp*8;
        #pragma unroll
        for (int nt = 0; nt < 8; nt++) {
            int d = nt*8 + 2*lq;
            __half2 hv = __floats2half2_rn(o[nt][rp*2] * inv, o[nt][rp*2 + 1] * inv);
            *(__half2*)&g_attn[((size_t)(b * S_ + row)) * D_ + h * 64 + d] = hv;
        }
    }
}

// ---------------------------------------------------------------------------
extern "C" void kernel_launch(void* const* d_in, const int* in_sizes, int n_in,
                              void* d_out, int out_size)
{
    const float* x      = (const float*)d_in[0];
    const float* w_qkv  = (const float*)d_in[1];
    const float* b_qkv  = (const float*)d_in[2];
    const float* w_proj = (const float*)d_in[3];
    const float* b_proj = (const float*)d_in[4];
    float* out = (float*)d_out;

    pre_round_x<<<512, 256>>>(x);
    transpose_round<<<dim3(N3_/32, D_/32), dim3(32, 8)>>>(w_qkv, N3_, 0);
    transpose_round<<<dim3(D_/32,  D_/32), dim3(32, 8)>>>(w_proj, D_, 1);

    int gsmem = 2 * GSTG_HALFS * (int)sizeof(__half);   // 40960 B
    cudaFuncSetAttribute(gemm_h<true>,
                         cudaFuncAttributeMaxDynamicSharedMemorySize, gsmem);
    cudaFuncSetAttribute(gemm_h<false>,
                         cudaFuncAttributeMaxDynamicSharedMemorySize, gsmem);

    dim3 g1(N3_/128, M_/128);   // (18, 64)
    gemm_h<true><<<g1, 256, gsmem>>>(b_qkv, nullptr);

    int asmem = 2 * TSZ * (int)sizeof(float) + 64 * KSP * (int)sizeof(__half); // 44032
    cudaFuncSetAttribute(flash_attn_h,
                         cudaFuncAttributeMaxDynamicSharedMemorySize, asmem);
    flash_attn_h<<<B_ * H_ * (S_/64), 128, asmem>>>();

    dim3 g2(D_/128, M_/128);    // (6, 64)
    gemm_h<false><<<g2, 256, gsmem>>>(b_proj, out);
}

// round 8
// speedup vs baseline: 2.0260x; 1.4085x over previous
#include <cuda_runtime.h>
#include <cuda_fp16.h>
#include <math.h>
#include <stdint.h>

#define B_  4
#define S_  2048
#define D_  768
#define H_  12
#define HD_ 64
#define N3_ (3*D_)
#define M_  (B_*S_)

// Scratch (allocation-free rule: __device__ globals)
__device__ __half g_q[B_*H_*S_*HD_];    // [b,h,s,d] fp16
__device__ __half g_k[B_*H_*S_*HD_];    // [b,h,s,d] fp16
__device__ __half g_v[B_*H_*HD_*S_];    // [b,h,d,s] fp16  (TRANSPOSED)
__device__ __half g_attn[M_*D_];        // [b,s, h*64+d] fp16
__device__ __half g_x[M_*D_];           // fp16 x
__device__ __half g_wq[N3_*D_];         // w_qkv^T  [N3][K] fp16
__device__ __half g_wp[D_*D_];          // w_proj^T [N][K]  fp16

// ---------------------------------------------------------------------------
// helpers
// ---------------------------------------------------------------------------
__device__ __forceinline__ void mma16(float c[4], const uint32_t a[4], const uint32_t b[2]) {
    asm("mma.sync.aligned.m16n8k16.row.col.f32.f16.f16.f32 "
        "{%0,%1,%2,%3},{%4,%5,%6,%7},{%8,%9},{%0,%1,%2,%3};"
        : "+f"(c[0]), "+f"(c[1]), "+f"(c[2]), "+f"(c[3])
        : "r"(a[0]), "r"(a[1]), "r"(a[2]), "r"(a[3]), "r"(b[0]), "r"(b[1]));
}
__device__ __forceinline__ uint32_t hbits(const __half* p) {
    return *reinterpret_cast<const uint32_t*>(p);
}
__device__ __forceinline__ void cp16(uint32_t sdst, const void* gsrc) {
    asm volatile("cp.async.cg.shared.global [%0], [%1], 16;" :: "r"(sdst), "l"(gsrc));
}
__device__ __forceinline__ void cp_commit() {
    asm volatile("cp.async.commit_group;" ::: "memory");
}
__device__ __forceinline__ uint32_t s2u(const void* p) {
    return (uint32_t)__cvta_generic_to_shared(p);
}

// ---------------------------------------------------------------------------
// pre-round: x -> fp16 ; weights -> transposed [N][K] fp16
// ---------------------------------------------------------------------------
__global__ void pre_round_x(const float* __restrict__ x)
{
    const float4* src = (const float4*)x;
    __half2* dst = (__half2*)g_x;
    int n4 = (M_*D_)/4;
    for (int i = blockIdx.x * blockDim.x + threadIdx.x; i < n4;
         i += gridDim.x * blockDim.x) {
        float4 v = src[i];
        dst[i*2]   = __floats2half2_rn(v.x, v.y);
        dst[i*2+1] = __floats2half2_rn(v.z, v.w);
    }
}

__global__ void transpose_round(const float* __restrict__ src, int cols, int which)
{
    __shared__ float t[32][33];
    __half* dst = which ? g_wp : g_wq;   // [cols][768]
    int c0 = blockIdx.x * 32, r0 = blockIdx.y * 32;
    int x = threadIdx.x, y = threadIdx.y;   // 32 x 8
    #pragma unroll
    for (int i = y; i < 32; i += 8)
        t[i][x] = src[(size_t)(r0 + i) * cols + c0 + x];
    __syncthreads();
    #pragma unroll
    for (int i = y; i < 32; i += 8)
        dst[(size_t)(c0 + i) * D_ + r0 + x] = __float2half_rn(t[x][i]);
}

// ---------------------------------------------------------------------------
// fp16 GEMM, cp.async 2-stage: C[M x N] = A[M x 768] @ Wt[N x 768]^T + bias
// CTA 128x128 (k-tile 32), 256 threads, 8 warps (4x2), warp tile 32x64.
// ---------------------------------------------------------------------------
#define GAP 40
#define GA_HALFS (128*GAP)
#define GSTG_HALFS (2*GA_HALFS)

template<bool QKV>
__global__ __launch_bounds__(256, 2) void gemm_h(
    const float* __restrict__ bias, float* __restrict__ C)
{
    extern __shared__ __half hsm[];
    const int K = D_;
    int tid = threadIdx.x, bx = blockIdx.x, by = blockIdx.y;
    int lane = tid & 31, wid = tid >> 5, lg = lane >> 2, lq = lane & 3;
    int wm = (wid >> 1) * 32, wn = (wid & 1) * 64;

    const __half* Ab = QKV ? (const __half*)g_x  : (const __half*)g_attn;
    const __half* Bt = QKV ? (const __half*)g_wq : (const __half*)g_wp;

    int r = tid >> 1, p = tid & 1;
    const __half* asrc = Ab + (size_t)(by * 128 + r) * K + p * 16;
    const __half* bsrc = Bt + (size_t)(bx * 128 + r) * K + p * 16;
    uint32_t a_s = s2u(hsm) + (r * GAP + p * 16) * 2;
    uint32_t b_s = s2u(hsm) + (GA_HALFS + r * GAP + p * 16) * 2;

    float acc[2][8][4];
    #pragma unroll
    for (int mt = 0; mt < 2; mt++)
        #pragma unroll
        for (int nt = 0; nt < 8; nt++)
            #pragma unroll
            for (int i = 0; i < 4; i++) acc[mt][nt][i] = 0.f;

    #define GLOAD(ch, st) do {                                  \
        uint32_t ao = a_s + (st) * (GSTG_HALFS * 2);            \
        uint32_t bo = b_s + (st) * (GSTG_HALFS * 2);            \
        const __half* ap = asrc + (ch) * 32;                    \
        const __half* bp = bsrc + (ch) * 32;                    \
        cp16(ao,      ap);     cp16(ao + 16, ap + 8);           \
        cp16(bo,      bp);     cp16(bo + 16, bp + 8);           \
        cp_commit();                                            \
    } while (0)

    GLOAD(0, 0);

    for (int it = 0; it < 24; it++) {
        if (it < 23) {
            GLOAD(it + 1, (it + 1) & 1);
            asm volatile("cp.async.wait_group 1;" ::: "memory");
        } else {
            asm volatile("cp.async.wait_group 0;" ::: "memory");
        }
        __syncthreads();

        const __half* As = hsm + (it & 1) * GSTG_HALFS;
        const __half* Bs = As + GA_HALFS;

        #pragma unroll
        for (int ks = 0; ks < 2; ks++) {
            int kr = ks * 16;
            uint32_t af[2][4], bf[8][2];
            #pragma unroll
            for (int mt = 0; mt < 2; mt++) {
                int r0 = (wm + mt * 16 + lg) * GAP;
                af[mt][0] = hbits(&As[r0           + kr + 2*lq    ]);
                af[mt][1] = hbits(&As[r0 + 8 * GAP + kr + 2*lq    ]);
                af[mt][2] = hbits(&As[r0           + kr + 2*lq + 8]);
                af[mt][3] = hbits(&As[r0 + 8 * GAP + kr + 2*lq + 8]);
            }
            #pragma unroll
            for (int nt = 0; nt < 8; nt++) {
                int nr = (wn + nt * 8 + lg) * GAP;
                bf[nt][0] = hbits(&Bs[nr + kr + 2*lq    ]);
                bf[nt][1] = hbits(&Bs[nr + kr + 2*lq + 8]);
            }
            #pragma unroll
            for (int mt = 0; mt < 2; mt++)
                #pragma unroll
                for (int nt = 0; nt < 8; nt++)
                    mma16(acc[mt][nt], af[mt], bf[nt]);
        }
        __syncthreads();
    }

    // Epilogue
    #pragma unroll
    for (int mt = 0; mt < 2; mt++) {
        #pragma unroll
        for (int rp = 0; rp < 2; rp++) {
            int m = by * 128 + wm + mt * 16 + lg + rp * 8;
            if (QKV) {
                int bb = m >> 11;
                int ss = m & (S_ - 1);
                #pragma unroll
                for (int nt = 0; nt < 8; nt++) {
                    int n = bx * 128 + wn + nt * 8 + 2 * lq;
                    int which = n / D_;
                    int rem = n - which * D_;
                    int hh = rem >> 6, dd = rem & 63;
                    float vx = acc[mt][nt][rp*2 + 0] + bias[n];
                    float vy = acc[mt][nt][rp*2 + 1] + bias[n + 1];
                    if (which == 2) {
                        // V transposed: [b,h,d,s]
                        size_t vi = ((size_t)(bb * H_ + hh) * HD_ + dd) * S_ + ss;
                        g_v[vi]      = __float2half_rn(vx);
                        g_v[vi + S_] = __float2half_rn(vy);
                    } else {
                        __half* dst = (which == 0) ? g_q : g_k;
                        size_t idx = (((size_t)(bb * H_ + hh) * S_ + ss) << 6) + dd;
                        *(__half2*)&dst[idx] = __floats2half2_rn(vx, vy);
                    }
                }
            } else {
                #pragma unroll
                for (int nt = 0; nt < 8; nt++) {
                    int n = bx * 128 + wn + nt * 8 + 2 * lq;
                    float2 v;
                    v.x = acc[mt][nt][rp*2 + 0] + bias[n];
                    v.y = acc[mt][nt][rp*2 + 1] + bias[n + 1];
                    *(float2*)&C[(size_t)m * D_ + n] = v;
                }
            }
        }
    }
}

// ---------------------------------------------------------------------------
// Flash attention, causal, all-fp16 operands (fp32 accum + softmax).
// One block = (b, h, 64-row q tile); 128 threads; warp w owns rows [w*16,+16).
// SMEM: Ks[64][72]h ([s_k][d]), Vs[64][72]h ([d][s_k]), Ps[64][72]h.
// ---------------------------------------------------------------------------
#define KSP 72
#define ATILE (64*KSP)

__global__ __launch_bounds__(128) void flash_attn_h()
{
    extern __shared__ __half hsm[];
    __half* Ks = hsm;
    __half* Vs = hsm + ATILE;
    __half* Ps = hsm + 2*ATILE;

    int bid = blockIdx.x;
    int qt = 31 - (bid & 31);
    int h  = (bid >> 5) % H_;
    int b  = bid / (32 * H_);
    int tid = threadIdx.x;
    int lane = tid & 31, w = tid >> 5, lg = lane >> 2, lq = lane & 3;
    int q0 = qt * 64;

    const __half* Qg = g_q + (size_t)(b * H_ + h) * S_ * HD_;
    const __half* Kg = g_k + (size_t)(b * H_ + h) * S_ * HD_;
    const __half* Vg = g_v + (size_t)(b * H_ + h) * HD_ * S_;   // [d][s]

    // K: row = s_k, 128B of d.  V: row = d, 128B of s_k.
    int r_ = tid >> 1, p_ = tid & 1;
    uint32_t ks_u = s2u(Ks) + (r_ * KSP + p_ * 32) * 2;
    uint32_t vs_u = s2u(Vs) + (r_ * KSP + p_ * 32) * 2;
    const __half* kg_row = Kg + (size_t)r_ * 64 + p_ * 32;      // advance by s
    const __half* vg_row = Vg + (size_t)r_ * S_ + p_ * 32;      // advance by s (cols)

    // Q fragments straight from global, scaled by 0.125 (exact in fp16)
    const __half2 sc2 = __floats2half2_rn(0.125f, 0.125f);
    uint32_t qf[4][4];
    {
        const __half* qr0 = Qg + (size_t)(q0 + w*16 + lg    ) * 64;
        const __half* qr1 = Qg + (size_t)(q0 + w*16 + lg + 8) * 64;
        #pragma unroll
        for (int ks = 0; ks < 4; ks++) {
            int kc = ks * 16 + 2 * lq;
            uint32_t t0 = hbits(qr0 + kc),     t1 = hbits(qr1 + kc);
            uint32_t t2 = hbits(qr0 + kc + 8), t3 = hbits(qr1 + kc + 8);
            __half2 h0 = __hmul2(*(__half2*)&t0, sc2);
            __half2 h1 = __hmul2(*(__half2*)&t1, sc2);
            __half2 h2 = __hmul2(*(__half2*)&t2, sc2);
            __half2 h3 = __hmul2(*(__half2*)&t3, sc2);
            qf[ks][0] = *(uint32_t*)&h0; qf[ks][1] = *(uint32_t*)&h1;
            qf[ks][2] = *(uint32_t*)&h2; qf[ks][3] = *(uint32_t*)&h3;
        }
    }

    float mrow[2] = {-INFINITY, -INFINITY};
    float lrow[2] = {0.f, 0.f};
    float o[8][4];
    #pragma unroll
    for (int nt = 0; nt < 8; nt++)
        #pragma unroll
        for (int i = 0; i < 4; i++) o[nt][i] = 0.f;

    for (int kt = 0; kt <= qt; kt++) {
        __syncthreads();   // prior reads of Ks/Vs done
        {
            const __half* kp = kg_row + (size_t)kt * 64 * 64;   // K rows advance
            const __half* vp = vg_row + (size_t)kt * 64;        // V cols advance
            #pragma unroll
            for (int j = 0; j < 4; j++) cp16(ks_u + j * 16, kp + j * 8);
            #pragma unroll
            for (int j = 0; j < 4; j++) cp16(vs_u + j * 16, vp + j * 8);
            cp_commit();
        }
        asm volatile("cp.async.wait_group 0;" ::: "memory");
        __syncthreads();

        // S = (Q*scale) @ K^T   (fp16 mma, 4 k-steps)
        float s[8][4];
        #pragma unroll
        for (int nt = 0; nt < 8; nt++)
            #pragma unroll
            for (int i = 0; i < 4; i++) s[nt][i] = 0.f;

        #pragma unroll
        for (int ks = 0; ks < 4; ks++) {
            int kr = ks * 16 + 2 * lq;
            uint32_t bv[8][2];
            #pragma unroll
            for (int nt = 0; nt < 8; nt++) {
                int nr = (nt * 8 + lg) * KSP;
                bv[nt][0] = hbits(&Ks[nr + kr    ]);
                bv[nt][1] = hbits(&Ks[nr + kr + 8]);
            }
            #pragma unroll
            for (int nt = 0; nt < 8; nt++)
                mma16(s[nt], qf[ks], bv[nt]);
        }

        if (kt == qt) {   // diagonal tile: causal mask
            #pragma unroll
            for (int nt = 0; nt < 8; nt++)
                #pragma unroll
                for (int rp = 0; rp < 2; rp++)
                    #pragma unroll
                    for (int j = 0; j < 2; j++) {
                        int col = nt*8 + 2*lq + j;
                        int row = w*16 + lg + rp*8;
                        if (col > row) s[nt][rp*2 + j] = -INFINITY;
                    }
        }

        // Online softmax (thread owns rows lg, lg+8 of warp tile)
        #pragma unroll
        for (int rp = 0; rp < 2; rp++) {
            float mt = -INFINITY;
            #pragma unroll
            for (int nt = 0; nt < 8; nt++)
                mt = fmaxf(mt, fmaxf(s[nt][rp*2], s[nt][rp*2 + 1]));
            mt = fmaxf(mt, __shfl_xor_sync(0xffffffffu, mt, 1));
            mt = fmaxf(mt, __shfl_xor_sync(0xffffffffu, mt, 2));
            float mnew = fmaxf(mrow[rp], mt);
            float alpha = __expf(mrow[rp] - mnew);
            float rs = 0.f;
            #pragma unroll
            for (int nt = 0; nt < 8; nt++) {
                float e0 = __expf(s[nt][rp*2]     - mnew);
                float e1 = __expf(s[nt][rp*2 + 1] - mnew);
                s[nt][rp*2] = e0; s[nt][rp*2 + 1] = e1;
                rs += e0 + e1;
            }
            rs += __shfl_xor_sync(0xffffffffu, rs, 1);
            rs += __shfl_xor_sync(0xffffffffu, rs, 2);
            lrow[rp] = lrow[rp] * alpha + rs;
            mrow[rp] = mnew;
            #pragma unroll
            for (int nt = 0; nt < 8; nt++) {
                o[nt][rp*2]     *= alpha;
                o[nt][rp*2 + 1] *= alpha;
            }
            // P -> fp16 SMEM (row-major [q][k])
            #pragma unroll
            for (int nt = 0; nt < 8; nt++) {
                *(__half2*)&Ps[(w*16 + lg + rp*8) * KSP + nt*8 + 2*lq] =
                    __floats2half2_rn(s[nt][rp*2], s[nt][rp*2 + 1]);
            }
        }
        __syncwarp();

        // O += P @ V   (fp16 mma, 4 k-steps; B-frag from transposed Vs)
        #pragma unroll
        for (int ks = 0; ks < 4; ks++) {
            int kr = ks * 16 + 2 * lq;
            uint32_t pa[4];
            pa[0] = hbits(&Ps[(w*16 + lg    ) * KSP + kr    ]);
            pa[1] = hbits(&Ps[(w*16 + lg + 8) * KSP + kr    ]);
            pa[2] = hbits(&Ps[(w*16 + lg    ) * KSP + kr + 8]);
            pa[3] = hbits(&Ps[(w*16 + lg + 8) * KSP + kr + 8]);
            uint32_t bv[8][2];
            #pragma unroll
            for (int nt = 0; nt < 8; nt++) {
                int nr = (nt * 8 + lg) * KSP;
                bv[nt][0] = hbits(&Vs[nr + kr    ]);
                bv[nt][1] = hbits(&Vs[nr + kr + 8]);
            }
            #pragma unroll
            for (int nt = 0; nt < 8; nt++)
                mma16(o[nt], pa, bv[nt]);
        }
        __syncwarp();
    }

    // Normalize, fp16-round (proj A operand), write [b, s, h*64+d]
    #pragma unroll
    for (int rp = 0; rp < 2; rp++) {
        float inv = 1.f / lrow[rp];
        int row = q0 + w*16 + lg + rp*8;
        #pragma unroll
        for (int nt = 0; nt < 8; nt++) {
            int d = nt*8 + 2*lq;
            __half2 hv = __floats2half2_rn(o[nt][rp*2] * inv, o[nt][rp*2 + 1] * inv);
            *(__half2*)&g_attn[((size_t)(b * S_ + row)) * D_ + h * 64 + d] = hv;
        }
    }
}

// ---------------------------------------------------------------------------
extern "C" void kernel_launch(void* const* d_in, const int* in_sizes, int n_in,
                              void* d_out, int out_size)
{
    const float* x      = (const float*)d_in[0];
    const float* w_qkv  = (const float*)d_in[1];
    const float* b_qkv  = (const float*)d_in[2];
    const float* w_proj = (const float*)d_in[3];
    const float* b_proj = (const float*)d_in[4];
    float* out = (float*)d_out;

    pre_round_x<<<512, 256>>>(x);
    transpose_round<<<dim3(N3_/32, D_/32), dim3(32, 8)>>>(w_qkv, N3_, 0);
    transpose_round<<<dim3(D_/32,  D_/32), dim3(32, 8)>>>(w_proj, D_, 1);

    int gsmem = 2 * GSTG_HALFS * (int)sizeof(__half);   // 40960 B
    cudaFuncSetAttribute(gemm_h<true>,
                         cudaFuncAttributeMaxDynamicSharedMemorySize, gsmem);
    cudaFuncSetAttribute(gemm_h<false>,
                         cudaFuncAttributeMaxDynamicSharedMemorySize, gsmem);

    dim3 g1(N3_/128, M_/128);   // (18, 64)
    gemm_h<true><<<g1, 256, gsmem>>>(b_qkv, nullptr);

    int asmem = 3 * ATILE * (int)sizeof(__half);        // 27648 B
    cudaFuncSetAttribute(flash_attn_h,
                         cudaFuncAttributeMaxDynamicSharedMemorySize, asmem);
    flash_attn_h<<<B_ * H_ * (S_/64), 128, asmem>>>();

    dim3 g2(D_/128, M_/128);    // (6, 64)
    gemm_h<false><<<g2, 256, gsmem>>>(b_proj, out);
}

// round 9
// speedup vs baseline: 2.2198x; 1.0956x over previous
#include <cuda_runtime.h>
#include <cuda_fp16.h>
#include <math.h>
#include <stdint.h>

#define B_  4
#define S_  2048
#define D_  768
#define H_  12
#define HD_ 64
#define N3_ (3*D_)
#define M_  (B_*S_)

// Scratch (allocation-free rule: __device__ globals)
__device__ __half g_q[B_*H_*S_*HD_];    // [b,h,s,d] fp16
__device__ __half g_k[B_*H_*S_*HD_];    // [b,h,s,d] fp16
__device__ __half g_v[B_*H_*HD_*S_];    // [b,h,d,s] fp16  (TRANSPOSED)
__device__ __half g_attn[M_*D_];        // [b,s, h*64+d] fp16
__device__ __half g_x[M_*D_];           // fp16 x
__device__ __half g_wq[N3_*D_];         // w_qkv^T  [N3][K] fp16
__device__ __half g_wp[D_*D_];          // w_proj^T [N][K]  fp16

// ---------------------------------------------------------------------------
// helpers
// ---------------------------------------------------------------------------
__device__ __forceinline__ void mma16(float c[4], const uint32_t a[4], const uint32_t b[2]) {
    asm("mma.sync.aligned.m16n8k16.row.col.f32.f16.f16.f32 "
        "{%0,%1,%2,%3},{%4,%5,%6,%7},{%8,%9},{%0,%1,%2,%3};"
        : "+f"(c[0]), "+f"(c[1]), "+f"(c[2]), "+f"(c[3])
        : "r"(a[0]), "r"(a[1]), "r"(a[2]), "r"(a[3]), "r"(b[0]), "r"(b[1]));
}
__device__ __forceinline__ void ldsm4(uint32_t r[4], uint32_t addr) {
    asm volatile("ldmatrix.sync.aligned.m8n8.x4.shared.b16 {%0,%1,%2,%3}, [%4];"
        : "=r"(r[0]), "=r"(r[1]), "=r"(r[2]), "=r"(r[3]) : "r"(addr));
}
__device__ __forceinline__ void cp16(uint32_t sdst, const void* gsrc) {
    asm volatile("cp.async.cg.shared.global [%0], [%1], 16;" :: "r"(sdst), "l"(gsrc));
}
__device__ __forceinline__ void cp_commit() {
    asm volatile("cp.async.commit_group;" ::: "memory");
}
__device__ __forceinline__ uint32_t s2u(const void* p) {
    return (uint32_t)__cvta_generic_to_shared(p);
}
__device__ __forceinline__ uint32_t h2bits(__half2 h) {
    return *reinterpret_cast<uint32_t*>(&h);
}

// ---------------------------------------------------------------------------
// pre-round: x -> fp16 ; weights -> transposed [N][K] fp16
// ---------------------------------------------------------------------------
__global__ void pre_round_x(const float* __restrict__ x)
{
    const float4* src = (const float4*)x;
    __half2* dst = (__half2*)g_x;
    int n4 = (M_*D_)/4;
    for (int i = blockIdx.x * blockDim.x + threadIdx.x; i < n4;
         i += gridDim.x * blockDim.x) {
        float4 v = src[i];
        dst[i*2]   = __floats2half2_rn(v.x, v.y);
        dst[i*2+1] = __floats2half2_rn(v.z, v.w);
    }
}

__global__ void transpose_round(const float* __restrict__ src, int cols, int which)
{
    __shared__ float t[32][33];
    __half* dst = which ? g_wp : g_wq;   // [cols][768]
    int c0 = blockIdx.x * 32, r0 = blockIdx.y * 32;
    int x = threadIdx.x, y = threadIdx.y;   // 32 x 8
    #pragma unroll
    for (int i = y; i < 32; i += 8)
        t[i][x] = src[(size_t)(r0 + i) * cols + c0 + x];
    __syncthreads();
    #pragma unroll
    for (int i = y; i < 32; i += 8)
        dst[(size_t)(c0 + i) * D_ + r0 + x] = __float2half_rn(t[x][i]);
}

// ---------------------------------------------------------------------------
// fp16 GEMM, cp.async 2-stage + ldmatrix: C = A[M,768] @ Wt[N,768]^T + bias
// CTA 128x128 (k-tile 32), 256 threads, 8 warps (4x2), warp tile 32x64.
// ---------------------------------------------------------------------------
#define GAP 40
#define GA_HALFS (128*GAP)
#define GSTG_HALFS (2*GA_HALFS)

template<bool QKV>
__global__ __launch_bounds__(256, 2) void gemm_h(
    const float* __restrict__ bias, float* __restrict__ C)
{
    extern __shared__ __half hsm[];
    const int K = D_;
    int tid = threadIdx.x, bx = blockIdx.x, by = blockIdx.y;
    int lane = tid & 31, wid = tid >> 5, lg = lane >> 2, lq = lane & 3;
    int wm = (wid >> 1) * 32, wn = (wid & 1) * 64;

    const __half* Ab = QKV ? (const __half*)g_x  : (const __half*)g_attn;
    const __half* Bt = QKV ? (const __half*)g_wq : (const __half*)g_wp;

    int r = tid >> 1, p = tid & 1;
    const __half* asrc = Ab + (size_t)(by * 128 + r) * K + p * 16;
    const __half* bsrc = Bt + (size_t)(bx * 128 + r) * K + p * 16;
    uint32_t a_s = s2u(hsm) + (r * GAP + p * 16) * 2;
    uint32_t b_s = s2u(hsm) + (GA_HALFS + r * GAP + p * 16) * 2;

    // ldmatrix lane offsets (bytes, relative to stage base)
    uint32_t offA[2], offB[4];
    {
        int arow = (lane & 15), acol = (lane >> 4) << 3;    // halves
        #pragma unroll
        for (int mt = 0; mt < 2; mt++)
            offA[mt] = ((wm + mt * 16 + arow) * GAP + acol) * 2;
        int brow = ((lane >> 4) << 3) + (lane & 7);
        int bcol = ((lane >> 3) & 1) << 3;
        #pragma unroll
        for (int ntp = 0; ntp < 4; ntp++)
            offB[ntp] = (uint32_t)(GA_HALFS + (wn + ntp * 16 + brow) * GAP + bcol) * 2;
    }

    float acc[2][8][4];
    #pragma unroll
    for (int mt = 0; mt < 2; mt++)
        #pragma unroll
        for (int nt = 0; nt < 8; nt++)
            #pragma unroll
            for (int i = 0; i < 4; i++) acc[mt][nt][i] = 0.f;

    #define GLOAD(ch, st) do {                                  \
        uint32_t ao = a_s + (st) * (GSTG_HALFS * 2);            \
        uint32_t bo = b_s + (st) * (GSTG_HALFS * 2);            \
        const __half* ap = asrc + (ch) * 32;                    \
        const __half* bp = bsrc + (ch) * 32;                    \
        cp16(ao,      ap);     cp16(ao + 16, ap + 8);           \
        cp16(bo,      bp);     cp16(bo + 16, bp + 8);           \
        cp_commit();                                            \
    } while (0)

    GLOAD(0, 0);

    for (int it = 0; it < 24; it++) {
        if (it < 23) {
            GLOAD(it + 1, (it + 1) & 1);
            asm volatile("cp.async.wait_group 1;" ::: "memory");
        } else {
            asm volatile("cp.async.wait_group 0;" ::: "memory");
        }
        __syncthreads();

        uint32_t sb = s2u(hsm) + (it & 1) * (GSTG_HALFS * 2);

        #pragma unroll
        for (int ks = 0; ks < 2; ks++) {
            uint32_t kadd = ks * 32;   // 16 halves
            uint32_t af[2][4], bf[8][2];
            #pragma unroll
            for (int mt = 0; mt < 2; mt++)
                ldsm4(af[mt], sb + offA[mt] + kadd);
            #pragma unroll
            for (int ntp = 0; ntp < 4; ntp++) {
                uint32_t t[4];
                ldsm4(t, sb + offB[ntp] + kadd);
                bf[2*ntp][0] = t[0]; bf[2*ntp][1] = t[1];
                bf[2*ntp+1][0] = t[2]; bf[2*ntp+1][1] = t[3];
            }
            #pragma unroll
            for (int mt = 0; mt < 2; mt++)
                #pragma unroll
                for (int nt = 0; nt < 8; nt++)
                    mma16(acc[mt][nt], af[mt], bf[nt]);
        }
        __syncthreads();
    }

    // Epilogue
    #pragma unroll
    for (int mt = 0; mt < 2; mt++) {
        #pragma unroll
        for (int rp = 0; rp < 2; rp++) {
            int m = by * 128 + wm + mt * 16 + lg + rp * 8;
            if (QKV) {
                int bb = m >> 11;
                int ss = m & (S_ - 1);
                #pragma unroll
                for (int nt = 0; nt < 8; nt++) {
                    int n = bx * 128 + wn + nt * 8 + 2 * lq;
                    int which = n / D_;
                    int rem = n - which * D_;
                    int hh = rem >> 6, dd = rem & 63;
                    float vx = acc[mt][nt][rp*2 + 0] + bias[n];
                    float vy = acc[mt][nt][rp*2 + 1] + bias[n + 1];
                    if (which == 2) {
                        size_t vi = ((size_t)(bb * H_ + hh) * HD_ + dd) * S_ + ss;
                        g_v[vi]      = __float2half_rn(vx);
                        g_v[vi + S_] = __float2half_rn(vy);
                    } else {
                        __half* dst = (which == 0) ? g_q : g_k;
                        size_t idx = (((size_t)(bb * H_ + hh) * S_ + ss) << 6) + dd;
                        *(__half2*)&dst[idx] = __floats2half2_rn(vx, vy);
                    }
                }
            } else {
                #pragma unroll
                for (int nt = 0; nt < 8; nt++) {
                    int n = bx * 128 + wn + nt * 8 + 2 * lq;
                    float2 v;
                    v.x = acc[mt][nt][rp*2 + 0] + bias[n];
                    v.y = acc[mt][nt][rp*2 + 1] + bias[n + 1];
                    *(float2*)&C[(size_t)m * D_ + n] = v;
                }
            }
        }
    }
}

// ---------------------------------------------------------------------------
// Flash attention, causal, all-fp16 mma, ldmatrix K/V, register-resident P.
// One block = (b, h, 64-row q tile); 128 threads; warp w owns rows [w*16,+16).
// SMEM: Ks[64][72]h ([s_k][d]), Vs[64][72]h ([d][s_k]).
// ---------------------------------------------------------------------------
#define KSP 72
#define ATILE (64*KSP)

__global__ __launch_bounds__(128) void flash_attn_h()
{
    extern __shared__ __half hsm[];
    __half* Ks = hsm;
    __half* Vs = hsm + ATILE;

    int bid = blockIdx.x;
    int qt = 31 - (bid & 31);
    int h  = (bid >> 5) % H_;
    int b  = bid / (32 * H_);
    int tid = threadIdx.x;
    int lane = tid & 31, w = tid >> 5, lg = lane >> 2, lq = lane & 3;
    int q0 = qt * 64;

    const __half* Qg = g_q + (size_t)(b * H_ + h) * S_ * HD_;
    const __half* Kg = g_k + (size_t)(b * H_ + h) * S_ * HD_;
    const __half* Vg = g_v + (size_t)(b * H_ + h) * HD_ * S_;   // [d][s]

    int r_ = tid >> 1, p_ = tid & 1;
    uint32_t ks_u = s2u(Ks) + (r_ * KSP + p_ * 32) * 2;
    uint32_t vs_u = s2u(Vs) + (r_ * KSP + p_ * 32) * 2;
    const __half* kg_row = Kg + (size_t)r_ * 64 + p_ * 32;
    const __half* vg_row = Vg + (size_t)r_ * S_ + p_ * 32;

    // ldmatrix lane offsets for K/V B-fragments (rows = nt*8+lg pattern)
    uint32_t offK[4], offV[4];
    {
        int brow = ((lane >> 4) << 3) + (lane & 7);
        int bcol = ((lane >> 3) & 1) << 3;
        #pragma unroll
        for (int ntp = 0; ntp < 4; ntp++) {
            offK[ntp] = s2u(Ks) + ((ntp * 16 + brow) * KSP + bcol) * 2;
            offV[ntp] = s2u(Vs) + ((ntp * 16 + brow) * KSP + bcol) * 2;
        }
    }

    // Q fragments straight from global, scaled by 0.125 (exact in fp16)
    const __half2 sc2 = __floats2half2_rn(0.125f, 0.125f);
    uint32_t qf[4][4];
    {
        const __half* qr0 = Qg + (size_t)(q0 + w*16 + lg    ) * 64;
        const __half* qr1 = Qg + (size_t)(q0 + w*16 + lg + 8) * 64;
        #pragma unroll
        for (int ks = 0; ks < 4; ks++) {
            int kc = ks * 16 + 2 * lq;
            __half2 h0 = __hmul2(*(const __half2*)(qr0 + kc),     sc2);
            __half2 h1 = __hmul2(*(const __half2*)(qr1 + kc),     sc2);
            __half2 h2 = __hmul2(*(const __half2*)(qr0 + kc + 8), sc2);
            __half2 h3 = __hmul2(*(const __half2*)(qr1 + kc + 8), sc2);
            qf[ks][0] = h2bits(h0); qf[ks][1] = h2bits(h1);
            qf[ks][2] = h2bits(h2); qf[ks][3] = h2bits(h3);
        }
    }

    float mrow[2] = {-INFINITY, -INFINITY};
    float lrow[2] = {0.f, 0.f};
    float o[8][4];
    #pragma unroll
    for (int nt = 0; nt < 8; nt++)
        #pragma unroll
        for (int i = 0; i < 4; i++) o[nt][i] = 0.f;

    for (int kt = 0; kt <= qt; kt++) {
        __syncthreads();   // prior LDSM reads of Ks/Vs done
        {
            const __half* kp = kg_row + (size_t)kt * 64 * 64;
            const __half* vp = vg_row + (size_t)kt * 64;
            #pragma unroll
            for (int j = 0; j < 4; j++) cp16(ks_u + j * 16, kp + j * 8);
            #pragma unroll
            for (int j = 0; j < 4; j++) cp16(vs_u + j * 16, vp + j * 8);
            cp_commit();
        }
        asm volatile("cp.async.wait_group 0;" ::: "memory");
        __syncthreads();

        // S = (Q*scale) @ K^T   (fp16 mma, 4 k-steps, ldmatrix K)
        float s[8][4];
        #pragma unroll
        for (int nt = 0; nt < 8; nt++)
            #pragma unroll
            for (int i = 0; i < 4; i++) s[nt][i] = 0.f;

        #pragma unroll
        for (int ks = 0; ks < 4; ks++) {
            uint32_t kadd = ks * 32;
            uint32_t bv[8][2];
            #pragma unroll
            for (int ntp = 0; ntp < 4; ntp++) {
                uint32_t t[4];
                ldsm4(t, offK[ntp] + kadd);
                bv[2*ntp][0] = t[0]; bv[2*ntp][1] = t[1];
                bv[2*ntp+1][0] = t[2]; bv[2*ntp+1][1] = t[3];
            }
            #pragma unroll
            for (int nt = 0; nt < 8; nt++)
                mma16(s[nt], qf[ks], bv[nt]);
        }

        if (kt == qt) {   // diagonal tile: causal mask
            #pragma unroll
            for (int nt = 0; nt < 8; nt++)
                #pragma unroll
                for (int rp = 0; rp < 2; rp++)
                    #pragma unroll
                    for (int j = 0; j < 2; j++) {
                        int col = nt*8 + 2*lq + j;
                        int row = w*16 + lg + rp*8;
                        if (col > row) s[nt][rp*2 + j] = -INFINITY;
                    }
        }

        // Online softmax (thread owns rows lg, lg+8 of warp tile)
        #pragma unroll
        for (int rp = 0; rp < 2; rp++) {
            float mt = -INFINITY;
            #pragma unroll
            for (int nt = 0; nt < 8; nt++)
                mt = fmaxf(mt, fmaxf(s[nt][rp*2], s[nt][rp*2 + 1]));
            mt = fmaxf(mt, __shfl_xor_sync(0xffffffffu, mt, 1));
            mt = fmaxf(mt, __shfl_xor_sync(0xffffffffu, mt, 2));
            float mnew = fmaxf(mrow[rp], mt);
            float alpha = __expf(mrow[rp] - mnew);
            float rs = 0.f;
            #pragma unroll
            for (int nt = 0; nt < 8; nt++) {
                float e0 = __expf(s[nt][rp*2]     - mnew);
                float e1 = __expf(s[nt][rp*2 + 1] - mnew);
                s[nt][rp*2] = e0; s[nt][rp*2 + 1] = e1;
                rs += e0 + e1;
            }
            rs += __shfl_xor_sync(0xffffffffu, rs, 1);
            rs += __shfl_xor_sync(0xffffffffu, rs, 2);
            lrow[rp] = lrow[rp] * alpha + rs;
            mrow[rp] = mnew;
            #pragma unroll
            for (int nt = 0; nt < 8; nt++) {
                o[nt][rp*2]     *= alpha;
                o[nt][rp*2 + 1] *= alpha;
            }
        }

        // O += P @ V : P's C-fragment reinterpreted as A-fragment in registers
        #pragma unroll
        for (int ks = 0; ks < 4; ks++) {
            uint32_t pa[4];
            pa[0] = h2bits(__floats2half2_rn(s[2*ks][0],   s[2*ks][1]));
            pa[1] = h2bits(__floats2half2_rn(s[2*ks][2],   s[2*ks][3]));
            pa[2] = h2bits(__floats2half2_rn(s[2*ks+1][0], s[2*ks+1][1]));
            pa[3] = h2bits(__floats2half2_rn(s[2*ks+1][2], s[2*ks+1][3]));
            uint32_t kadd = ks * 32;
            uint32_t bv[8][2];
            #pragma unroll
            for (int ntp = 0; ntp < 4; ntp++) {
                uint32_t t[4];
                ldsm4(t, offV[ntp] + kadd);
                bv[2*ntp][0] = t[0]; bv[2*ntp][1] = t[1];
                bv[2*ntp+1][0] = t[2]; bv[2*ntp+1][1] = t[3];
            }
            #pragma unroll
            for (int nt = 0; nt < 8; nt++)
                mma16(o[nt], pa, bv[nt]);
        }
    }

    // Normalize, fp16-round (proj A operand), write [b, s, h*64+d]
    #pragma unroll
    for (int rp = 0; rp < 2; rp++) {
        float inv = 1.f / lrow[rp];
        int row = q0 + w*16 + lg + rp*8;
        #pragma unroll
        for (int nt = 0; nt < 8; nt++) {
            int d = nt*8 + 2*lq;
            __half2 hv = __floats2half2_rn(o[nt][rp*2] * inv, o[nt][rp*2 + 1] * inv);
            *(__half2*)&g_attn[((size_t)(b * S_ + row)) * D_ + h * 64 + d] = hv;
        }
    }
}

// ---------------------------------------------------------------------------
extern "C" void kernel_launch(void* const* d_in, const int* in_sizes, int n_in,
                              void* d_out, int out_size)
{
    const float* x      = (const float*)d_in[0];
    const float* w_qkv  = (const float*)d_in[1];
    const float* b_qkv  = (const float*)d_in[2];
    const float* w_proj = (const float*)d_in[3];
    const float* b_proj = (const float*)d_in[4];
    float* out = (float*)d_out;

    pre_round_x<<<512, 256>>>(x);
    transpose_round<<<dim3(N3_/32, D_/32), dim3(32, 8)>>>(w_qkv, N3_, 0);
    transpose_round<<<dim3(D_/32,  D_/32), dim3(32, 8)>>>(w_proj, D_, 1);

    int gsmem = 2 * GSTG_HALFS * (int)sizeof(__half);   // 40960 B
    cudaFuncSetAttribute(gemm_h<true>,
                         cudaFuncAttributeMaxDynamicSharedMemorySize, gsmem);
    cudaFuncSetAttribute(gemm_h<false>,
                         cudaFuncAttributeMaxDynamicSharedMemorySize, gsmem);

    dim3 g1(N3_/128, M_/128);   // (18, 64)
    gemm_h<true><<<g1, 256, gsmem>>>(b_qkv, nullptr);

    int asmem = 2 * ATILE * (int)sizeof(__half);        // 18432 B
    cudaFuncSetAttribute(flash_attn_h,
                         cudaFuncAttributeMaxDynamicSharedMemorySize, asmem);
    flash_attn_h<<<B_ * H_ * (S_/64), 128, asmem>>>();

    dim3 g2(D_/128, M_/128);    // (6, 64)
    gemm_h<false><<<g2, 256, gsmem>>>(b_proj, out);
}